// round 2
// baseline (speedup 1.0000x reference)
#include <cuda_runtime.h>
#include <math.h>

#define BB 4
#define CC 64
#define HH 128
#define WW 128
#define NT 256

// Scratch buffers (allocation-free: __device__ globals)
__device__ float d_buf_o[BB*CC*HH*WW];
__device__ float d_buf_r[BB*CC*HH*WW];   // resblock temp / MFE branch accumulator
__device__ float d_buf_t[BB*CC*HH*WW];   // MFE branch first-conv temp
__device__ float d_stats[2*BB*CC];       // [0:256) max, [256:512) avg
__device__ float d_cg[BB*CC];

struct Epi {
    const float* bias;   // [64] slice (per-oc), may be null
    const float* res;    // residual add (resblock), may be null
    const float* acc;    // branch accumulator add, may be null
    const float* cg;     // per (b,oc) output scale, may be null
    const float* map;    // final: [B,H,W], may be null
    const float* xres;   // final: original x, used iff map set
    float* out;
    int act;             // 0 none, 1 relu, 2 lrelu(0.01)
};

// Direct conv, pad = K/2, stride 1. Block: 32x32 spatial tile x 8 output channels.
// 256 threads: tx = tid&7 -> 4 consecutive cols, ty = tid>>3 -> row.
template<int K>
__global__ __launch_bounds__(NT) void conv_kernel(
    const float* __restrict__ in,      // [B,C,H,W] (batch base applied inside)
    const float* __restrict__ w,       // [64,64,K,K] slice
    float wscale,
    const float* __restrict__ cond,    // [B*64] per-(b,ic) input scale or null
    Epi e)
{
    constexpr int PAD = K/2;
    constexpr int TH = 32, TW = 32, OCB = 8;
    constexpr int IHS = TH + 2*PAD, IWS = TW + 2*PAD;
    constexpr int STR = (IWS % 2 == 0) ? IWS + 1 : IWS;  // odd -> conflict-free

    __shared__ float s_in[IHS*STR];
    __shared__ float s_w[OCB*K*K];

    const int tid = threadIdx.x;
    const int tx = tid & 7;        // col group
    const int ty = tid >> 3;       // row 0..31
    const int bx = blockIdx.x, by = blockIdx.y;
    const int b  = blockIdx.z >> 3;
    const int ocg = blockIdx.z & 7;
    const int gy0 = by*TH, gx0 = bx*TW;

    float acc[OCB][4];
    #pragma unroll
    for (int o = 0; o < OCB; o++)
        #pragma unroll
        for (int c = 0; c < 4; c++) acc[o][c] = 0.f;

    const float* inb = in + (size_t)b*CC*HH*WW;

    for (int ic = 0; ic < CC; ic++) {
        const float cs = cond ? cond[b*CC + ic] : 1.f;
        const float* inc = inb + (size_t)ic*HH*WW;
        // load padded input tile
        for (int idx = tid; idx < IHS*IWS; idx += NT) {
            const int r = idx / IWS, c = idx % IWS;
            const int gh = gy0 + r - PAD, gw = gx0 + c - PAD;
            float v = 0.f;
            if (gh >= 0 && gh < HH && gw >= 0 && gw < WW)
                v = inc[gh*WW + gw] * cs;
            s_in[r*STR + c] = v;
        }
        // load this ic's weights for 8 ocs
        if (tid < OCB*K*K) {
            const int o = tid / (K*K), k = tid % (K*K);
            s_w[tid] = w[(((size_t)(ocg*OCB + o))*CC + ic)*(K*K) + k] * wscale;
        }
        __syncthreads();

        // pull this thread's input window into registers
        float r_in[K][K+3];
        #pragma unroll
        for (int kh = 0; kh < K; kh++)
            #pragma unroll
            for (int cc = 0; cc < K+3; cc++)
                r_in[kh][cc] = s_in[(ty + kh)*STR + 4*tx + cc];

        #pragma unroll
        for (int o = 0; o < OCB; o++) {
            #pragma unroll
            for (int kh = 0; kh < K; kh++)
                #pragma unroll
                for (int kw = 0; kw < K; kw++) {
                    const float wv = s_w[o*K*K + kh*K + kw];
                    #pragma unroll
                    for (int c = 0; c < 4; c++)
                        acc[o][c] = fmaf(r_in[kh][kw + c], wv, acc[o][c]);
                }
        }
        __syncthreads();
    }

    // epilogue
    const int oh = gy0 + ty;
    #pragma unroll
    for (int o = 0; o < OCB; o++) {
        const int oc = ocg*OCB + o;
        const float bv  = e.bias ? e.bias[oc] : 0.f;
        const float cgv = e.cg ? e.cg[b*CC + oc] : 1.f;
        #pragma unroll
        for (int c = 0; c < 4; c++) {
            const int ow = gx0 + 4*tx + c;
            const size_t idx = (((size_t)b*CC + oc)*HH + oh)*WW + ow;
            float v = acc[o][c] + bv;
            if (e.act == 1)      v = fmaxf(v, 0.f);
            else if (e.act == 2) v = (v > 0.f) ? v : 0.01f*v;
            if (e.res) v += e.res[idx];
            if (e.acc) v += e.acc[idx];
            v *= cgv;
            if (e.map) v = v * e.map[(size_t)b*HH*WW + oh*WW + ow] + e.xres[idx];
            e.out[idx] = v;
        }
    }
}

// Per-(b,c) max + mean over HxW
__global__ __launch_bounds__(NT) void stats_kernel(const float* __restrict__ in,
                                                   float* __restrict__ st)
{
    const int bc = blockIdx.x;                // 0..255
    const float* p = in + (size_t)bc*HH*WW;
    const int tid = threadIdx.x;
    float mx = -3.4e38f, sm = 0.f;
    for (int i = tid; i < HH*WW; i += NT) {
        const float v = p[i];
        mx = fmaxf(mx, v);
        sm += v;
    }
    __shared__ float smx[NT], ssm[NT];
    smx[tid] = mx; ssm[tid] = sm;
    __syncthreads();
    for (int s = NT/2; s > 0; s >>= 1) {
        if (tid < s) {
            smx[tid] = fmaxf(smx[tid], smx[tid+s]);
            ssm[tid] += ssm[tid+s];
        }
        __syncthreads();
    }
    if (tid == 0) {
        st[bc] = smx[0];
        st[BB*CC + bc] = ssm[0] * (1.f/(HH*WW));
    }
}

// Channel attention -> Cg  (one block, 256 threads, thread = (b,c))
__global__ void cg_kernel(const float* __restrict__ st,
                          const float* __restrict__ cw1,  // [4,64]
                          const float* __restrict__ cw2,  // [64,4]
                          const float* __restrict__ fw,   // [2]
                          const float* __restrict__ fb,   // [2]
                          float* __restrict__ cg)
{
    const int t = threadIdx.x;
    const int b = t >> 6, c = t & 63;
    float se = 0.f;
    #pragma unroll
    for (int h = 0; h < 4; h++) {
        float hm = 0.f, ha = 0.f;
        for (int i = 0; i < CC; i++) {
            const float wv = cw1[h*CC + i];
            hm += wv * st[b*CC + i];
            ha += wv * st[BB*CC + b*CC + i];
        }
        hm = fmaxf(hm, 0.f);
        ha = fmaxf(ha, 0.f);
        se += cw2[c*4 + h] * (hm + ha);
    }
    const float xll = 1.f / (1.f + expf(-se));
    cg[t] = fw[1]*(fw[0]*xll + fb[0]) + fb[1];
}

static Epi mkEpi(const float* bias, int act, float* out) {
    Epi e;
    e.bias = bias; e.res = nullptr; e.acc = nullptr; e.cg = nullptr;
    e.map = nullptr; e.xres = nullptr; e.out = out; e.act = act;
    return e;
}

extern "C" void kernel_launch(void* const* d_in, const int* in_sizes, int n_in,
                              void* d_out, int out_size)
{
    const float* x    = (const float*)d_in[0];
    const float* cf1  = (const float*)d_in[1];  // [5,2,B,1,C,1,1]
    const float* cf2  = (const float*)d_in[2];  // [4,2,B,1,C,1,1]
    const float* map_ = (const float*)d_in[3];  // [B,1,H,W]
    const float* resw = (const float*)d_in[4];  // [9,2,C,C,3,3]
    const float* resb = (const float*)d_in[5];  // [9,2,C]
    const float* mw1  = (const float*)d_in[6];  // [5,2,C,C,1,1]
    const float* mb1  = (const float*)d_in[7];
    const float* mw3  = (const float*)d_in[8];  // [5,2,C,C,3,3]
    const float* mb3  = (const float*)d_in[9];
    const float* mw5  = (const float*)d_in[10]; // [5,2,C,C,5,5]
    const float* mb5  = (const float*)d_in[11];
    const float* caw1 = (const float*)d_in[12]; // [5,4,64]
    const float* caw2 = (const float*)d_in[13]; // [5,64,4]
    const float* fcw  = (const float*)d_in[14]; // [5,2]
    const float* fcb  = (const float*)d_in[15]; // [5,2]
    float* out = (float*)d_out;

    float *bo, *br, *bt, *bst, *bcg;
    cudaGetSymbolAddress((void**)&bo,  d_buf_o);
    cudaGetSymbolAddress((void**)&br,  d_buf_r);
    cudaGetSymbolAddress((void**)&bt,  d_buf_t);
    cudaGetSymbolAddress((void**)&bst, d_stats);
    cudaGetSymbolAddress((void**)&bcg, d_cg);

    const float SCALE = 1.0f / 24.0f;   // 1/sqrt(64*9)
    const dim3 grid(WW/32, HH/32, BB*8);
    const dim3 blk(NT);

    const int mfe_after[9] = {-1, 0, -1, 1, -1, 2, -1, 3, 4};
    const float* cur = x;

    for (int i = 0; i < 9; i++) {
        // ---- resblock i ----
        const float* c0 = (i < 5) ? cf1 + (size_t)(i*2+0)*BB*CC
                                  : cf2 + (size_t)((i-5)*2+0)*BB*CC;
        const float* c1 = c0 + BB*CC;
        const float* w0 = resw + (size_t)(i*2+0)*CC*CC*9;
        const float* w1 = resw + (size_t)(i*2+1)*CC*CC*9;

        Epi e1 = mkEpi(resb + (size_t)(i*2+0)*CC, /*relu*/1, br);
        conv_kernel<3><<<grid, blk>>>(cur, w0, SCALE, c0, e1);

        Epi e2 = mkEpi(resb + (size_t)(i*2+1)*CC, /*none*/0, bo);
        e2.res = cur;                                   // + x residual
        conv_kernel<3><<<grid, blk>>>(br, w1, SCALE, c1, e2);
        cur = bo;

        // ---- MFE j (if any) ----
        const int j = mfe_after[i];
        if (j >= 0) {
            stats_kernel<<<BB*CC, blk>>>(cur, bst);
            cg_kernel<<<1, blk>>>(bst, caw1 + (size_t)j*4*CC, caw2 + (size_t)j*CC*4,
                                  fcw + j*2, fcb + j*2, bcg);

            // branch 1x1: cur -> bt (lrelu) -> br (init acc)
            Epi a1 = mkEpi(mb1 + (size_t)(j*2+0)*CC, 2, bt);
            conv_kernel<1><<<grid, blk>>>(cur, mw1 + (size_t)(j*2+0)*CC*CC, 1.f, nullptr, a1);
            Epi b1 = mkEpi(mb1 + (size_t)(j*2+1)*CC, 0, br);
            conv_kernel<1><<<grid, blk>>>(bt, mw1 + (size_t)(j*2+1)*CC*CC, 1.f, nullptr, b1);

            // branch 3x3: cur -> bt (lrelu) -> br (+= acc, in place)
            Epi a3 = mkEpi(mb3 + (size_t)(j*2+0)*CC, 2, bt);
            conv_kernel<3><<<grid, blk>>>(cur, mw3 + (size_t)(j*2+0)*CC*CC*9, 1.f, nullptr, a3);
            Epi b3 = mkEpi(mb3 + (size_t)(j*2+1)*CC, 0, br);
            b3.acc = br;
            conv_kernel<3><<<grid, blk>>>(bt, mw3 + (size_t)(j*2+1)*CC*CC*9, 1.f, nullptr, b3);

            // branch 5x5: cur -> bt (lrelu) -> final (Cg*(acc+this) [, *map + x])
            Epi a5 = mkEpi(mb5 + (size_t)(j*2+0)*CC, 2, bt);
            conv_kernel<5><<<grid, blk>>>(cur, mw5 + (size_t)(j*2+0)*CC*CC*25, 1.f, nullptr, a5);

            Epi b5 = mkEpi(mb5 + (size_t)(j*2+1)*CC, 0, (j == 4) ? out : bo);
            b5.acc = br;
            b5.cg  = bcg;
            if (j == 4) { b5.map = map_; b5.xres = x; }
            conv_kernel<5><<<grid, blk>>>(bt, mw5 + (size_t)(j*2+1)*CC*CC*25, 1.f, nullptr, b5);
            cur = bo;
        }
    }
}

// round 4
// speedup vs baseline: 5.2625x; 5.2625x over previous
#include <cuda_runtime.h>
#include <cuda_bf16.h>
#include <stdint.h>
#include <math.h>

#define BB 4
#define CC 64
#define HH 128
#define WW 128

// ---------------- scratch (__device__ globals: allocation-free) ----------------
__device__ float d_buf_o[BB*CC*HH*WW];
__device__ float d_buf_r[BB*CC*HH*WW];
__device__ float d_buf_t[BB*CC*HH*WW];
__device__ float d_stats[2*BB*CC];
__device__ float d_cg[BB*CC];
// 512 tap-tiles x (hi 8KB + lo 8KB) pre-swizzled [oc][ic] B matrices
__device__ __nv_bfloat16 d_wb[512*8192];

struct Epi { const float *bias,*res,*acc,*cg,*map,*xres; float* out; int act; };

// ---------------- helpers ----------------
__device__ __forceinline__ uint32_t smem_u32(const void* p){
    uint32_t a;
    asm("{ .reg .u64 t; cvta.to.shared.u64 t, %1; cvt.u32.u64 %0, t; }":"=r"(a):"l"(p));
    return a;
}

#define LDSM4(r, a) \
    asm volatile("ldmatrix.sync.aligned.m8n8.x4.shared.b16 {%0,%1,%2,%3}, [%4];" \
        : "=r"((r)[0]),"=r"((r)[1]),"=r"((r)[2]),"=r"((r)[3]) : "r"(a))

__device__ __forceinline__ void mma16816(float* c, const uint32_t* a,
                                         uint32_t b0, uint32_t b1){
    asm volatile("mma.sync.aligned.m16n8k16.row.col.f32.bf16.bf16.f32 "
        "{%0,%1,%2,%3}, {%4,%5,%6,%7}, {%8,%9}, {%0,%1,%2,%3};"
        : "+f"(c[0]),"+f"(c[1]),"+f"(c[2]),"+f"(c[3])
        : "r"(a[0]),"r"(a[1]),"r"(a[2]),"r"(a[3]), "r"(b0),"r"(b1));
}

// swizzled byte offset for element (row, 16B-chunk), 128B rows
__device__ __forceinline__ uint32_t sw_addr(int row, int chunk){
    return ((uint32_t)row << 7) + (((uint32_t)(chunk ^ (row & 7))) << 4);
}

// ---------------- weight prep: fp32 -> hi/lo bf16, swizzled [oc][ic] tiles ----------------
// grid = nsets*kk; set-major tile order
__global__ void prep_kernel(const float* __restrict__ w, float scale, int kk, int dstbase){
    const int set = blockIdx.x / kk, tap = blockIdx.x % kk;
    const float* src = w + (size_t)set*CC*CC*kk;
    __nv_bfloat16* dst = d_wb + (size_t)(dstbase + blockIdx.x)*8192;
    for (int e = threadIdx.x; e < 4096; e += 256){
        const int oc = e >> 6, ic = e & 63;
        const float v = src[(size_t)(oc*CC+ic)*kk + tap] * scale;
        const __nv_bfloat16 hb = __float2bfloat16(v);
        const __nv_bfloat16 lb = __float2bfloat16(v - __bfloat162float(hb));
        const uint32_t off = (uint32_t)oc*128 + (uint32_t)ic*2;
        const uint32_t sw = off ^ ((off>>3)&0x70);
        dst[sw>>1] = hb;
        dst[4096 + (sw>>1)] = lb;
    }
}

// ---------------- mma.sync implicit-GEMM conv: one CTA = (b,h), D[128w][64oc] ----------------
template<int K>
__global__ __launch_bounds__(256) void conv_mma(
    const float* __restrict__ in, const __nv_bfloat16* __restrict__ wtap,
    const float* __restrict__ cond, Epi e)
{
    constexpr int PAD = K/2;
    constexpr int WP  = WW + 2*PAD;      // padded pixel rows in A
    constexpr int ALO = WP*128;          // A-lo offset
    constexpr int BO  = 2*WP*128;        // B-hi offset (B-lo = BO+8192)

    extern __shared__ char smraw[];
    const uint32_t sb0 = smem_u32(smraw);
    const uint32_t sb  = (sb0 + 127) & ~127u;          // 128B align
    char* sm = smraw + (sb - sb0);

    const int tid = threadIdx.x;
    const int l   = tid & 31;
    const int wid = tid >> 5;
    const int m0  = (wid & 3) * 32;      // warp m base (pixel)
    const int n0  = (wid >> 2) * 32;     // warp n base (oc)
    const int h = blockIdx.x, b = blockIdx.y;

    float acc[2][4][4];
    #pragma unroll
    for (int mt = 0; mt < 2; mt++)
        #pragma unroll
        for (int nt = 0; nt < 4; nt++)
            #pragma unroll
            for (int q = 0; q < 4; q++) acc[mt][nt][q] = 0.f;

    for (int kh = 0; kh < K; kh++){
        const int hp = h + kh - PAD;
        __syncthreads();                 // previous tap's mma done before restage
        // ---- stage A: padded row, hi/lo bf16, cond folded ----
        const bool hok = (hp >= 0 && hp < HH);
        for (int i = tid; i < CC*WP; i += 256){
            const int ic = i / WP, p = i - ic*WP;
            const int w = p - PAD;
            float v = 0.f;
            if (hok && w >= 0 && w < WW)
                v = in[(((size_t)b*CC+ic)*HH + hp)*WW + w];
            if (cond) v *= cond[b*CC + ic];
            const __nv_bfloat16 hb = __float2bfloat16(v);
            const __nv_bfloat16 lb = __float2bfloat16(v - __bfloat162float(hb));
            const uint32_t off = ((uint32_t)p << 7) + ((uint32_t)ic << 1);
            const uint32_t sw = off ^ ((off>>3)&0x70);
            *(__nv_bfloat16*)(sm + sw)       = hb;
            *(__nv_bfloat16*)(sm + ALO + sw) = lb;
        }

        for (int kw = 0; kw < K; kw++){
            __syncthreads();             // A staged / previous mma done before B overwrite
            // ---- copy B tap tile (hi+lo, 16KB) ----
            {
                const uint4* src = (const uint4*)(wtap + (size_t)(kh*K+kw)*8192);
                uint4* dst = (uint4*)(sm + BO);
                #pragma unroll
                for (int j = 0; j < 4; j++) dst[tid + j*256] = src[tid + j*256];
            }
            __syncthreads();

            // ---- 4 k-steps of 16 ic ----
            #pragma unroll
            for (int ks = 0; ks < 4; ks++){
                uint32_t ah[2][4], al[2][4];
                #pragma unroll
                for (int mt = 0; mt < 2; mt++){
                    const int row = m0 + mt*16 + kw + (l & 15);
                    const int ch  = ks*2 + (l >> 4);
                    const uint32_t ad = sb + sw_addr(row, ch);
                    LDSM4(ah[mt], ad);
                    LDSM4(al[mt], ad + ALO);
                }
                uint32_t bh[2][4], bl[2][4];
                #pragma unroll
                for (int np = 0; np < 2; np++){
                    const int row = n0 + np*16 + (l & 15);
                    const int ch  = ks*2 + (l >> 4);
                    const uint32_t bd = sb + BO + sw_addr(row, ch);
                    LDSM4(bh[np], bd);
                    LDSM4(bl[np], bd + 8192);
                }
                #pragma unroll
                for (int mt = 0; mt < 2; mt++)
                    #pragma unroll
                    for (int nt = 0; nt < 4; nt++){
                        const uint32_t b0h = bh[nt>>1][nt&1], b1h = bh[nt>>1][2+(nt&1)];
                        const uint32_t b0l = bl[nt>>1][nt&1], b1l = bl[nt>>1][2+(nt&1)];
                        mma16816(acc[mt][nt], ah[mt], b0h, b1h);
                        mma16816(acc[mt][nt], al[mt], b0h, b1h);
                        mma16816(acc[mt][nt], ah[mt], b0l, b1l);
                    }
            }
        }
    }

    // ---- epilogue: acc -> smem transpose (stride 65 floats) -> coalesced gmem ----
    __syncthreads();
    float* os = (float*)sm;
    #pragma unroll
    for (int mt = 0; mt < 2; mt++)
        #pragma unroll
        for (int nt = 0; nt < 4; nt++)
            #pragma unroll
            for (int q = 0; q < 4; q++){
                const int row = m0 + mt*16 + (l>>2) + ((q>>1)<<3);
                const int col = n0 + nt*8 + ((l&3)<<1) + (q&1);
                os[row*65 + col] = acc[mt][nt][q];
            }
    __syncthreads();

    const int w = tid & 127;
    const int oc0 = (tid >> 7) * 32;
    const size_t pix = (size_t)h*WW + w;
    const float mv = e.map ? e.map[(size_t)b*HH*WW + pix] : 0.f;
    #pragma unroll 4
    for (int k = 0; k < 32; k++){
        const int oc = oc0 + k;
        const size_t idx = ((size_t)(b*CC+oc))*HH*WW + pix;
        float v = os[w*65 + oc];
        if (e.bias) v += e.bias[oc];
        if (e.act == 1)      v = fmaxf(v, 0.f);
        else if (e.act == 2) v = (v > 0.f) ? v : 0.01f*v;
        if (e.res) v += e.res[idx];
        if (e.acc) v += e.acc[idx];
        if (e.cg)  v *= e.cg[b*CC+oc];
        if (e.map) v = v*mv + e.xres[idx];
        e.out[idx] = v;
    }
}

// ---------------- stats + channel attention ----------------
__global__ __launch_bounds__(256) void stats_kernel(const float* __restrict__ in,
                                                    float* __restrict__ st){
    const int bc = blockIdx.x;
    const float* p = in + (size_t)bc*HH*WW;
    const int tid = threadIdx.x;
    float mx = -3.4e38f, smv = 0.f;
    for (int i = tid; i < HH*WW; i += 256){ const float v = p[i]; mx = fmaxf(mx, v); smv += v; }
    __shared__ float smx[256], ssm[256];
    smx[tid] = mx; ssm[tid] = smv; __syncthreads();
    for (int s = 128; s > 0; s >>= 1){
        if (tid < s){ smx[tid] = fmaxf(smx[tid], smx[tid+s]); ssm[tid] += ssm[tid+s]; }
        __syncthreads();
    }
    if (tid == 0){ st[bc] = smx[0]; st[BB*CC+bc] = ssm[0]*(1.f/(HH*WW)); }
}

__global__ void cg_kernel(const float* __restrict__ st, const float* __restrict__ cw1,
                          const float* __restrict__ cw2, const float* __restrict__ fw,
                          const float* __restrict__ fb, float* __restrict__ cg){
    const int t = threadIdx.x, b = t>>6, c = t&63;
    float se = 0.f;
    #pragma unroll
    for (int hh = 0; hh < 4; hh++){
        float hm = 0.f, ha = 0.f;
        for (int i = 0; i < CC; i++){
            const float wv = cw1[hh*CC+i];
            hm += wv*st[b*CC+i]; ha += wv*st[BB*CC+b*CC+i];
        }
        se += cw2[c*4+hh]*(fmaxf(hm,0.f)+fmaxf(ha,0.f));
    }
    const float xll = 1.f/(1.f+expf(-se));
    cg[t] = fw[1]*(fw[0]*xll+fb[0])+fb[1];
}

static Epi mkEpi(const float* bias, int act, float* out){
    Epi e; e.bias=bias; e.res=nullptr; e.acc=nullptr; e.cg=nullptr;
    e.map=nullptr; e.xres=nullptr; e.out=out; e.act=act; return e;
}

extern "C" void kernel_launch(void* const* d_in, const int* in_sizes, int n_in,
                              void* d_out, int out_size)
{
    const float* x    = (const float*)d_in[0];
    const float* cf1  = (const float*)d_in[1];
    const float* cf2  = (const float*)d_in[2];
    const float* map_ = (const float*)d_in[3];
    const float* resw = (const float*)d_in[4];
    const float* resb = (const float*)d_in[5];
    const float* mw1  = (const float*)d_in[6];
    const float* mb1  = (const float*)d_in[7];
    const float* mw3  = (const float*)d_in[8];
    const float* mb3  = (const float*)d_in[9];
    const float* mw5  = (const float*)d_in[10];
    const float* mb5  = (const float*)d_in[11];
    const float* caw1 = (const float*)d_in[12];
    const float* caw2 = (const float*)d_in[13];
    const float* fcw  = (const float*)d_in[14];
    const float* fcb  = (const float*)d_in[15];
    float* out = (float*)d_out;

    float *bo,*br,*bt,*bst,*bcg; __nv_bfloat16* wb;
    cudaGetSymbolAddress((void**)&bo,  d_buf_o);
    cudaGetSymbolAddress((void**)&br,  d_buf_r);
    cudaGetSymbolAddress((void**)&bt,  d_buf_t);
    cudaGetSymbolAddress((void**)&bst, d_stats);
    cudaGetSymbolAddress((void**)&bcg, d_cg);
    cudaGetSymbolAddress((void**)&wb,  d_wb);

    // smem sizes: 2*WP*128 + 16KB (+128 align slack)
    const int SM1 = 2*128*128 + 16384 + 128;
    const int SM3 = 2*130*128 + 16384 + 128;
    const int SM5 = 2*132*128 + 16384 + 128;
    cudaFuncSetAttribute(conv_mma<1>, cudaFuncAttributeMaxDynamicSharedMemorySize, SM1);
    cudaFuncSetAttribute(conv_mma<3>, cudaFuncAttributeMaxDynamicSharedMemorySize, SM3);
    cudaFuncSetAttribute(conv_mma<5>, cudaFuncAttributeMaxDynamicSharedMemorySize, SM5);

    const float SCALE = 1.0f/24.0f;
    // tap-tile bases (set-major)
    auto base_res=[](int i,int hf){return (i*2+hf)*9;};
    auto base_m1 =[](int j,int hf){return 162+(j*2+hf);};
    auto base_m3 =[](int j,int hf){return 172+(j*2+hf)*9;};
    auto base_m5 =[](int j,int hf){return 262+(j*2+hf)*25;};

    // batched weight prep: 4 launches
    prep_kernel<<<18*9, 256>>>(resw, SCALE, 9, 0);    // tiles [0,162)
    prep_kernel<<<10*1, 256>>>(mw1, 1.f, 1, 162);     // [162,172)
    prep_kernel<<<10*9, 256>>>(mw3, 1.f, 9, 172);     // [172,262)
    prep_kernel<<<10*25,256>>>(mw5, 1.f, 25, 262);    // [262,512)

    const dim3 grid(HH, BB), blk(256);
    const int mfe_after[9] = {-1,0,-1,1,-1,2,-1,3,4};
    const float* cur = x;

    for (int i = 0; i < 9; i++){
        const float* c0 = (i < 5) ? cf1+(size_t)(i*2)*BB*CC : cf2+(size_t)((i-5)*2)*BB*CC;
        const float* c1 = c0 + BB*CC;

        Epi e1 = mkEpi(resb+(size_t)(i*2+0)*CC, 1, br);
        conv_mma<3><<<grid,blk,SM3>>>(cur, wb+(size_t)base_res(i,0)*8192, c0, e1);
        Epi e2 = mkEpi(resb+(size_t)(i*2+1)*CC, 0, bo);
        e2.res = cur;
        conv_mma<3><<<grid,blk,SM3>>>(br, wb+(size_t)base_res(i,1)*8192, c1, e2);
        cur = bo;

        const int j = mfe_after[i];
        if (j >= 0){
            stats_kernel<<<BB*CC,256>>>(cur, bst);
            cg_kernel<<<1,256>>>(bst, caw1+(size_t)j*4*CC, caw2+(size_t)j*CC*4,
                                 fcw+j*2, fcb+j*2, bcg);

            Epi a1 = mkEpi(mb1+(size_t)(j*2+0)*CC, 2, bt);
            conv_mma<1><<<grid,blk,SM1>>>(cur, wb+(size_t)base_m1(j,0)*8192, nullptr, a1);
            Epi b1 = mkEpi(mb1+(size_t)(j*2+1)*CC, 0, br);
            conv_mma<1><<<grid,blk,SM1>>>(bt, wb+(size_t)base_m1(j,1)*8192, nullptr, b1);

            Epi a3 = mkEpi(mb3+(size_t)(j*2+0)*CC, 2, bt);
            conv_mma<3><<<grid,blk,SM3>>>(cur, wb+(size_t)base_m3(j,0)*8192, nullptr, a3);
            Epi b3 = mkEpi(mb3+(size_t)(j*2+1)*CC, 0, br);
            b3.acc = br;
            conv_mma<3><<<grid,blk,SM3>>>(bt, wb+(size_t)base_m3(j,1)*8192, nullptr, b3);

            Epi a5 = mkEpi(mb5+(size_t)(j*2+0)*CC, 2, bt);
            conv_mma<5><<<grid,blk,SM5>>>(cur, wb+(size_t)base_m5(j,0)*8192, nullptr, a5);

            Epi b5 = mkEpi(mb5+(size_t)(j*2+1)*CC, 0, (j == 4) ? out : bo);
            b5.acc = br; b5.cg = bcg;
            if (j == 4){ b5.map = map_; b5.xres = x; }
            conv_mma<5><<<grid,blk,SM5>>>(bt, wb+(size_t)base_m5(j,1)*8192, nullptr, b5);
            cur = bo;
        }
    }
}

// round 6
// speedup vs baseline: 6.8962x; 1.3104x over previous
#include <cuda_runtime.h>
#include <cuda_bf16.h>
#include <stdint.h>

#define BB 4
#define CC 64
#define HH 128
#define WW 128

// ---------------- scratch (__device__ globals: allocation-free) ----------------
__device__ float d_buf_o[BB*CC*HH*WW];
__device__ float d_buf_r[BB*CC*HH*WW];
__device__ float d_stats[2*BB*CC];
__device__ float d_cg[BB*CC];
// 998 tile-pairs (hi 4096 + lo 4096 bf16), pre-swizzled [oc][ic]
__device__ __align__(128) __nv_bfloat16 d_wb[998ull*8192];
// activation tiles: per (b,h) 16384 bf16 (hi 8192 + lo 8192), [w][ic] swizzled
// 0: x, 1: bo, 2: mid (resblock conv1 out / MFE a-conv out)
__device__ __align__(128) __nv_bfloat16 d_at[3][(size_t)BB*HH*16384];

struct Epi {
    const float *bias,*res,*acc,*cg,*map,*xres;
    float* out;                 // fp32 output (nullable)
    __nv_bfloat16* atout;       // atile output (nullable)
    int act;                    // 0 none, 1 relu, 2 lrelu(0.01)
};

// ---------------- helpers ----------------
__device__ __forceinline__ uint32_t smem_u32(const void* p){
    uint32_t a;
    asm("{ .reg .u64 t; cvta.to.shared.u64 t, %1; cvt.u32.u64 %0, t; }":"=r"(a):"l"(p));
    return a;
}
#define LDSM4(r, a) \
    asm volatile("ldmatrix.sync.aligned.m8n8.x4.shared.b16 {%0,%1,%2,%3}, [%4];" \
        : "=r"((r)[0]),"=r"((r)[1]),"=r"((r)[2]),"=r"((r)[3]) : "r"(a))

__device__ __forceinline__ void mma16816(float* c, const uint32_t* a,
                                         uint32_t b0, uint32_t b1){
    asm volatile("mma.sync.aligned.m16n8k16.row.col.f32.bf16.bf16.f32 "
        "{%0,%1,%2,%3}, {%4,%5,%6,%7}, {%8,%9}, {%0,%1,%2,%3};"
        : "+f"(c[0]),"+f"(c[1]),"+f"(c[2]),"+f"(c[3])
        : "r"(a[0]),"r"(a[1]),"r"(a[2]),"r"(a[3]), "r"(b0),"r"(b1));
}
__device__ __forceinline__ void split_pack(float v0, float v1, uint32_t& hp, uint32_t& lp){
    const __nv_bfloat16 h0=__float2bfloat16(v0), h1=__float2bfloat16(v1);
    const __nv_bfloat16 l0=__float2bfloat16(v0-__bfloat162float(h0));
    const __nv_bfloat16 l1=__float2bfloat16(v1-__bfloat162float(h1));
    hp = (uint32_t)__bfloat16_as_ushort(h0) | ((uint32_t)__bfloat16_as_ushort(h1)<<16);
    lp = (uint32_t)__bfloat16_as_ushort(l0) | ((uint32_t)__bfloat16_as_ushort(l1)<<16);
}

// ---------------- weight prep: fp32 (+cond) -> hi/lo bf16 swizzled [oc][ic] ----------------
// grid (k2, nb, nconv); cond nullable, laid out [(conv*nb+b)*64]
__global__ void prep2(const float* __restrict__ w, const float* __restrict__ cond,
                      float scale, int k2, int dstbase){
    const int tap=blockIdx.x, b=blockIdx.y, conv=blockIdx.z, nb=gridDim.y;
    const float* src = w + (size_t)conv*CC*CC*k2;
    const float* cp = cond ? cond + (size_t)(conv*nb+b)*CC : (const float*)0;
    __nv_bfloat16* dst = d_wb + (size_t)(dstbase + (conv*nb+b)*k2 + tap)*8192;
    for (int e=threadIdx.x; e<4096; e+=256){
        const int oc=e>>6, ic=e&63;
        float v = src[(size_t)(oc*CC+ic)*k2 + tap]*scale;
        if (cp) v *= cp[ic];
        const __nv_bfloat16 hb=__float2bfloat16(v);
        const __nv_bfloat16 lb=__float2bfloat16(v-__bfloat162float(hb));
        const uint32_t off=(uint32_t)oc*128+(uint32_t)ic*2;
        const uint32_t sw=off^((off>>3)&0x70);
        dst[sw>>1]=hb;
        dst[4096+(sw>>1)]=lb;
    }
}

// ---------------- ingest: x fp32 -> atile ----------------
__global__ __launch_bounds__(256) void ingest_kernel(const float* __restrict__ x,
                                                     __nv_bfloat16* __restrict__ xat){
    extern __shared__ char smI[];
    float* raw = (float*)smI;            // 32KB
    char*  at  = smI + 32768;            // 32KB
    const int tid=threadIdx.x, h=blockIdx.x, b=blockIdx.y;
    for (int i=tid;i<CC*WW;i+=256){
        const int ic=i>>7, w=i&127;
        raw[i] = x[(((size_t)b*CC+ic)*HH+h)*WW + w];
    }
    __syncthreads();
    const int w=tid&127, half=tid>>7;
    #pragma unroll
    for (int k=0;k<16;k++){
        const int ic=half*32+2*k;
        uint32_t hp, lp;
        split_pack(raw[ic*WW+w], raw[(ic+1)*WW+w], hp, lp);
        const uint32_t ro = (uint32_t)w*128 + ((uint32_t)((ic>>3)^(w&7))<<4) + (uint32_t)(ic&7)*2;
        *(uint32_t*)(at + ro) = hp;
        *(uint32_t*)(at + 16384 + ro) = lp;
    }
    __syncthreads();
    uint4* dst=(uint4*)(xat + (size_t)(b*HH+h)*16384);
    const uint4* src=(const uint4*)at;
    #pragma unroll
    for (int j=0;j<8;j++) dst[tid+j*256]=src[tid+j*256];
}

// ---------------- pipelined mma.sync implicit-GEMM conv: CTA=(b,h), D[128w][64oc] ----------------
template<int K>
__global__ __launch_bounds__(256,2) void conv_mma(
    const __nv_bfloat16* __restrict__ ain,   // atile input base
    const __nv_bfloat16* __restrict__ wt,    // tile-pair base
    int bstride,                             // tile pairs per batch (0 = shared)
    Epi e)
{
    constexpr int PAD=K/2, WP=WW+2*PAD, K2=K*K;
    constexpr int ALO = WP*128;      // lo plane byte offset within A buf
    constexpr int ASZ = WP*256;      // A buf bytes (hi+lo)
    constexpr int BOFF = 2*ASZ;      // B bufs base

    extern __shared__ char smraw[];
    const uint32_t sb0 = smem_u32(smraw);
    const uint32_t sb  = (sb0+127)&~127u;
    char* sm = smraw + (sb - sb0);

    const int tid=threadIdx.x, l=tid&31, wid=tid>>5;
    const int m0=(wid&3)*32, n0=(wid>>2)*32;
    const int h=blockIdx.x, b=blockIdx.y;

    // zero pad rows in both A buffers, hi+lo planes
    if (PAD>0){
        const int npad = 2*PAD;
        const int tot = 2*2*npad*8;          // bufs*planes*rows*uint4
        for (int i=tid;i<tot;i+=256){
            const int buf = i/(2*npad*8); int r1 = i%(2*npad*8);
            const int plane = r1/(npad*8); int r2 = r1%(npad*8);
            const int pr = r2/8, c = r2%8;
            const int row = (pr<PAD)? pr : (128+pr);
            ((uint4*)(sm + buf*ASZ + plane*ALO + row*128))[c] = make_uint4(0,0,0,0);
        }
    }

    const char* abase = (const char*)ain + (size_t)b*HH*32768;

    float acc[2][4][4];
    #pragma unroll
    for (int mt=0;mt<2;mt++)
        #pragma unroll
        for (int nt=0;nt<4;nt++)
            #pragma unroll
            for (int q=0;q<4;q++) acc[mt][nt][q]=0.f;

    auto issueA = [&](int kh){
        const int hp = h + kh - PAD;
        const int sz = (hp>=0 && hp<HH) ? 16 : 0;
        const int hpc = hp<0?0:(hp>127?127:hp);
        const char* src = abase + (size_t)hpc*32768;
        const uint32_t d0 = sb + (uint32_t)(kh&1)*ASZ + PAD*128;
        #pragma unroll
        for (int j=0;j<4;j++){
            const int c = tid + j*256;
            asm volatile("cp.async.cg.shared.global [%0], [%1], 16, %2;"
                :: "r"(d0 + c*16), "l"(src + c*16), "r"(sz) : "memory");
            asm volatile("cp.async.cg.shared.global [%0], [%1], 16, %2;"
                :: "r"(d0 + ALO + c*16), "l"(src + 16384 + c*16), "r"(sz) : "memory");
        }
    };
    auto issueB = [&](int t){
        const char* src = (const char*)(wt + ((size_t)b*bstride + t)*8192);
        const uint32_t d0 = sb + BOFF + (uint32_t)(t&1)*16384;
        #pragma unroll
        for (int j=0;j<4;j++){
            const int c = tid + j*256;
            asm volatile("cp.async.cg.shared.global [%0], [%1], 16;"
                :: "r"(d0 + c*16), "l"(src + c*16) : "memory");
        }
    };

    // prologue
    issueA(0);
    issueB(0);
    asm volatile("cp.async.commit_group;" ::: "memory");

    for (int t=0;t<K2;t++){
        const int kh=t/K, kw=t-kh*K;
        asm volatile("cp.async.wait_group 0;" ::: "memory");
        __syncthreads();
        if (t+1<K2){
            const int nt=t+1, nkh=nt/K;
            issueB(nt);
            if (nkh!=kh) issueA(nkh);
            asm volatile("cp.async.commit_group;" ::: "memory");
        }
        const int hp=h+kh-PAD;
        if (hp<0||hp>=HH) continue;

        const uint32_t aB = sb + (uint32_t)(kh&1)*ASZ;
        const uint32_t bB = sb + BOFF + (uint32_t)(t&1)*16384;
        #pragma unroll
        for (int ks=0;ks<4;ks++){
            const int ch = ks*2 + (l>>4);
            uint32_t ah[2][4], al[2][4];
            #pragma unroll
            for (int mt=0;mt<2;mt++){
                const int row = m0+mt*16+kw+(l&15);
                const uint32_t ad = aB + (uint32_t)row*128 +
                                    ((uint32_t)(ch ^ ((row-PAD)&7))<<4);
                LDSM4(ah[mt], ad);
                LDSM4(al[mt], ad + ALO);
            }
            uint32_t bh[2][4], bl[2][4];
            #pragma unroll
            for (int np=0;np<2;np++){
                const int row = n0+np*16+(l&15);
                const uint32_t bd = bB + (uint32_t)row*128 +
                                    ((uint32_t)(ch ^ (row&7))<<4);
                LDSM4(bh[np], bd);
                LDSM4(bl[np], bd + 8192);
            }
            #pragma unroll
            for (int mt=0;mt<2;mt++)
                #pragma unroll
                for (int nt=0;nt<4;nt++){
                    const uint32_t b0h=bh[nt>>1][nt&1], b1h=bh[nt>>1][2+(nt&1)];
                    const uint32_t b0l=bl[nt>>1][nt&1], b1l=bl[nt>>1][2+(nt&1)];
                    mma16816(acc[mt][nt], ah[mt], b0h, b1h);
                    mma16816(acc[mt][nt], al[mt], b0h, b1h);
                    mma16816(acc[mt][nt], ah[mt], b0l, b1l);
                }
        }
    }

    // ---- epilogue ----
    __syncthreads();
    float* os = (float*)sm;
    #pragma unroll
    for (int mt=0;mt<2;mt++)
        #pragma unroll
        for (int nt=0;nt<4;nt++)
            #pragma unroll
            for (int q=0;q<4;q++){
                const int row = m0+mt*16+(l>>2)+((q>>1)<<3);
                const int col = n0+nt*8+((l&3)<<1)+(q&1);
                os[row*65+col]=acc[mt][nt][q];
            }
    __syncthreads();

    const int w=tid&127, oc0=(tid>>7)*32;
    const size_t pix=(size_t)h*WW+w;
    const float mv = e.map? e.map[(size_t)b*HH*WW+pix] : 0.f;
    char* smA2 = sm + BOFF;
    #pragma unroll 4
    for (int k=0;k<32;k+=2){
        float vv[2];
        #pragma unroll
        for (int s=0;s<2;s++){
            const int oc=oc0+k+s;
            const size_t idx=((size_t)(b*CC+oc))*HH*WW+pix;
            float v=os[w*65+oc];
            if (e.bias) v+=e.bias[oc];
            if (e.act==1)      v=fmaxf(v,0.f);
            else if (e.act==2) v=(v>0.f)?v:0.01f*v;
            if (e.res) v+=e.res[idx];
            if (e.acc) v+=e.acc[idx];
            if (e.cg)  v*=e.cg[b*CC+oc];
            if (e.map) v=v*mv+e.xres[idx];
            if (e.out) e.out[idx]=v;
            vv[s]=v;
        }
        if (e.atout){
            const int oc=oc0+k;
            uint32_t hp, lp;
            split_pack(vv[0], vv[1], hp, lp);
            const uint32_t ro = (uint32_t)w*128 + ((uint32_t)((oc>>3)^(w&7))<<4)
                              + (uint32_t)(oc&7)*2;
            *(uint32_t*)(smA2 + ro) = hp;
            *(uint32_t*)(smA2 + 16384 + ro) = lp;
        }
    }
    if (e.atout){
        __syncthreads();
        uint4* dst=(uint4*)(e.atout + (size_t)(b*HH+h)*16384);
        const uint4* src=(const uint4*)smA2;
        #pragma unroll
        for (int j=0;j<8;j++) dst[tid+j*256]=src[tid+j*256];
    }
}

// ---------------- stats + channel attention ----------------
__global__ __launch_bounds__(256) void stats_kernel(const float* __restrict__ in,
                                                    float* __restrict__ st){
    const int bc=blockIdx.x;
    const float* p=in+(size_t)bc*HH*WW;
    const int tid=threadIdx.x;
    float mx=-3.4e38f, smv=0.f;
    for (int i=tid;i<HH*WW;i+=256){ const float v=p[i]; mx=fmaxf(mx,v); smv+=v; }
    __shared__ float smx[256], ssm[256];
    smx[tid]=mx; ssm[tid]=smv; __syncthreads();
    for (int s=128;s>0;s>>=1){
        if (tid<s){ smx[tid]=fmaxf(smx[tid],smx[tid+s]); ssm[tid]+=ssm[tid+s]; }
        __syncthreads();
    }
    if (tid==0){ st[bc]=smx[0]; st[BB*CC+bc]=ssm[0]*(1.f/(HH*WW)); }
}

__global__ void cg_kernel(const float* __restrict__ st, const float* __restrict__ cw1,
                          const float* __restrict__ cw2, const float* __restrict__ fw,
                          const float* __restrict__ fb, float* __restrict__ cg){
    const int t=threadIdx.x, b=t>>6, c=t&63;
    float se=0.f;
    #pragma unroll
    for (int hh=0;hh<4;hh++){
        float hm=0.f, ha=0.f;
        for (int i=0;i<CC;i++){
            const float wv=cw1[hh*CC+i];
            hm+=wv*st[b*CC+i]; ha+=wv*st[BB*CC+b*CC+i];
        }
        se+=cw2[c*4+hh]*(fmaxf(hm,0.f)+fmaxf(ha,0.f));
    }
    const float xll=1.f/(1.f+expf(-se));
    cg[t]=fw[1]*(fw[0]*xll+fb[0])+fb[1];
}

static Epi mkEpi(const float* bias, int act, float* out, __nv_bfloat16* atout){
    Epi e; e.bias=bias; e.res=nullptr; e.acc=nullptr; e.cg=nullptr;
    e.map=nullptr; e.xres=nullptr; e.out=out; e.atout=atout; e.act=act; return e;
}

extern "C" void kernel_launch(void* const* d_in, const int* in_sizes, int n_in,
                              void* d_out, int out_size)
{
    const float* x    = (const float*)d_in[0];
    const float* cf1  = (const float*)d_in[1];
    const float* cf2  = (const float*)d_in[2];
    const float* map_ = (const float*)d_in[3];
    const float* resw = (const float*)d_in[4];
    const float* resb = (const float*)d_in[5];
    const float* mw1  = (const float*)d_in[6];
    const float* mb1  = (const float*)d_in[7];
    const float* mw3  = (const float*)d_in[8];
    const float* mb3  = (const float*)d_in[9];
    const float* mw5  = (const float*)d_in[10];
    const float* mb5  = (const float*)d_in[11];
    const float* caw1 = (const float*)d_in[12];
    const float* caw2 = (const float*)d_in[13];
    const float* fcw  = (const float*)d_in[14];
    const float* fcb  = (const float*)d_in[15];
    float* out = (float*)d_out;

    float *bo,*br,*bst,*bcg; __nv_bfloat16 *wb,*at0;
    cudaGetSymbolAddress((void**)&bo,  d_buf_o);
    cudaGetSymbolAddress((void**)&br,  d_buf_r);
    cudaGetSymbolAddress((void**)&bst, d_stats);
    cudaGetSymbolAddress((void**)&bcg, d_cg);
    cudaGetSymbolAddress((void**)&wb,  d_wb);
    cudaGetSymbolAddress((void**)&at0, d_at);
    const size_t ATS = (size_t)BB*HH*16384;
    __nv_bfloat16* at_x   = at0;
    __nv_bfloat16* at_bo  = at0 + ATS;
    __nv_bfloat16* at_mid = at0 + 2*ATS;

    const int SM1 = 2*(128*256) + 32768 + 128;
    const int SM3 = 2*(130*256) + 32768 + 128;
    const int SM5 = 2*(132*256) + 32768 + 128;
    cudaFuncSetAttribute(conv_mma<1>, cudaFuncAttributeMaxDynamicSharedMemorySize, SM1);
    cudaFuncSetAttribute(conv_mma<3>, cudaFuncAttributeMaxDynamicSharedMemorySize, SM3);
    cudaFuncSetAttribute(conv_mma<5>, cudaFuncAttributeMaxDynamicSharedMemorySize, SM5);
    cudaFuncSetAttribute(ingest_kernel, cudaFuncAttributeMaxDynamicSharedMemorySize, 65536);

    const float SCALE = 1.0f/24.0f;

    // weight prep (cond folded for res convs)
    prep2<<<dim3(9,4,10), 256>>>(resw,                       cf1, SCALE, 9, 0);    // [0,360)
    prep2<<<dim3(9,4,8),  256>>>(resw+(size_t)10*CC*CC*9,    cf2, SCALE, 9, 360);  // [360,648)
    prep2<<<dim3(1,1,10), 256>>>(mw1,  nullptr, 1.f, 1,  648);                     // [648,658)
    prep2<<<dim3(9,1,10), 256>>>(mw3,  nullptr, 1.f, 9,  658);                     // [658,748)
    prep2<<<dim3(25,1,10),256>>>(mw5,  nullptr, 1.f, 25, 748);                     // [748,998)

    ingest_kernel<<<dim3(HH,BB),256,65536>>>(x, at_x);

    auto res_tb=[](int c){ return (c<10)? c*4*9 : 360+(c-10)*4*9; };

    const dim3 grid(HH,BB), blk(256);
    const int mfe_after[9]={-1,0,-1,1,-1,2,-1,3,4};
    const float* cur=x;
    __nv_bfloat16* cur_at=at_x;

    for (int i=0;i<9;i++){
        const int c0=i*2, c1=i*2+1;

        Epi e1=mkEpi(resb+(size_t)c0*CC, 1, nullptr, at_mid);
        conv_mma<3><<<grid,blk,SM3>>>(cur_at, wb+(size_t)res_tb(c0)*8192, 9, e1);

        Epi e2=mkEpi(resb+(size_t)c1*CC, 0, bo, at_bo);
        e2.res=cur;
        conv_mma<3><<<grid,blk,SM3>>>(at_mid, wb+(size_t)res_tb(c1)*8192, 9, e2);
        cur=bo; cur_at=at_bo;

        const int j=mfe_after[i];
        if (j>=0){
            stats_kernel<<<BB*CC,256>>>(cur,bst);
            cg_kernel<<<1,256>>>(bst, caw1+(size_t)j*4*CC, caw2+(size_t)j*CC*4,
                                 fcw+j*2, fcb+j*2, bcg);

            const int ca=j*2, cb=j*2+1;

            Epi a1=mkEpi(mb1+(size_t)ca*CC, 2, nullptr, at_mid);
            conv_mma<1><<<grid,blk,SM1>>>(cur_at, wb+(size_t)(648+ca)*8192, 0, a1);
            Epi b1=mkEpi(mb1+(size_t)cb*CC, 0, br, nullptr);
            conv_mma<1><<<grid,blk,SM1>>>(at_mid, wb+(size_t)(648+cb)*8192, 0, b1);

            Epi a3=mkEpi(mb3+(size_t)ca*CC, 2, nullptr, at_mid);
            conv_mma<3><<<grid,blk,SM3>>>(cur_at, wb+(size_t)(658+ca*9)*8192, 0, a3);
            Epi b3=mkEpi(mb3+(size_t)cb*CC, 0, br, nullptr);
            b3.acc=br;
            conv_mma<3><<<grid,blk,SM3>>>(at_mid, wb+(size_t)(658+cb*9)*8192, 0, b3);

            Epi a5=mkEpi(mb5+(size_t)ca*CC, 2, nullptr, at_mid);
            conv_mma<5><<<grid,blk,SM5>>>(cur_at, wb+(size_t)(748+ca*25)*8192, 0, a5);

            Epi b5=mkEpi(mb5+(size_t)cb*CC, 0, (j==4)?out:bo, (j==4)?nullptr:at_bo);
            b5.acc=br; b5.cg=bcg;
            if (j==4){ b5.map=map_; b5.xres=x; }
            conv_mma<5><<<grid,blk,SM5>>>(at_mid, wb+(size_t)(748+cb*25)*8192, 0, b5);
            cur=bo; cur_at=at_bo;
        }
    }
}

// round 7
// speedup vs baseline: 7.3945x; 1.0723x over previous
#include <cuda_runtime.h>
#include <cuda_bf16.h>
#include <stdint.h>

#define BB 4
#define CC 64
#define HH 128
#define WW 128

// ---------------- scratch (__device__ globals: allocation-free) ----------------
__device__ float d_buf_o[BB*CC*HH*WW];
__device__ float d_stats[2*BB*CC];
__device__ float d_cg[BB*CC];
// 998 tile-pairs (hi 4096 + lo 4096 bf16), pre-swizzled [oc][ic]
__device__ __align__(128) __nv_bfloat16 d_wb[998ull*8192];
// activation tiles: per (b,h) 16384 bf16 (hi 8192 + lo 8192), [w][ic] swizzled
// 0:x 1:bo 2:mid/m1 3:m3 4:m5
__device__ __align__(128) __nv_bfloat16 d_at[5][(size_t)BB*HH*16384];

struct Epi {
    const float *bias,*res,*cg,*map,*xres;
    float* out;                 // fp32 output (nullable)
    __nv_bfloat16* atout;       // atile output (nullable)
    int act;                    // 0 none, 1 relu, 2 lrelu(0.01)
};
struct Job {
    const __nv_bfloat16* ain;
    const __nv_bfloat16* wt;
    int bstride;                // tile pairs per batch (0 = shared)
    int kd;                     // 1/3/5
    Epi e;
};

// ---------------- helpers ----------------
__device__ __forceinline__ uint32_t smem_u32(const void* p){
    uint32_t a;
    asm("{ .reg .u64 t; cvta.to.shared.u64 t, %1; cvt.u32.u64 %0, t; }":"=r"(a):"l"(p));
    return a;
}
#define LDSM4(r, a) \
    asm volatile("ldmatrix.sync.aligned.m8n8.x4.shared.b16 {%0,%1,%2,%3}, [%4];" \
        : "=r"((r)[0]),"=r"((r)[1]),"=r"((r)[2]),"=r"((r)[3]) : "r"(a))

__device__ __forceinline__ void mma16816(float* c, const uint32_t* a,
                                         uint32_t b0, uint32_t b1){
    asm volatile("mma.sync.aligned.m16n8k16.row.col.f32.bf16.bf16.f32 "
        "{%0,%1,%2,%3}, {%4,%5,%6,%7}, {%8,%9}, {%0,%1,%2,%3};"
        : "+f"(c[0]),"+f"(c[1]),"+f"(c[2]),"+f"(c[3])
        : "r"(a[0]),"r"(a[1]),"r"(a[2]),"r"(a[3]), "r"(b0),"r"(b1));
}
__device__ __forceinline__ void split_pack(float v0, float v1, uint32_t& hp, uint32_t& lp){
    const __nv_bfloat16 h0=__float2bfloat16(v0), h1=__float2bfloat16(v1);
    const __nv_bfloat16 l0=__float2bfloat16(v0-__bfloat162float(h0));
    const __nv_bfloat16 l1=__float2bfloat16(v1-__bfloat162float(h1));
    hp = (uint32_t)__bfloat16_as_ushort(h0) | ((uint32_t)__bfloat16_as_ushort(h1)<<16);
    lp = (uint32_t)__bfloat16_as_ushort(l0) | ((uint32_t)__bfloat16_as_ushort(l1)<<16);
}

// unified A-buffer geometry (PAD=2 for all K)
#define WPU 132
#define ALOU (WPU*128)
#define ASZU (WPU*256)
#define BOFFU (2*ASZU)
#define SMEMSZ (BOFFU + 32768 + 128)

// ---------------- weight prep ----------------
__global__ void prep2(const float* __restrict__ w, const float* __restrict__ cond,
                      float scale, int k2, int dstbase){
    const int tap=blockIdx.x, b=blockIdx.y, conv=blockIdx.z, nb=gridDim.y;
    const float* src = w + (size_t)conv*CC*CC*k2;
    const float* cp = cond ? cond + (size_t)(conv*nb+b)*CC : (const float*)0;
    __nv_bfloat16* dst = d_wb + (size_t)(dstbase + (conv*nb+b)*k2 + tap)*8192;
    for (int e=threadIdx.x; e<4096; e+=256){
        const int oc=e>>6, ic=e&63;
        float v = src[(size_t)(oc*CC+ic)*k2 + tap]*scale;
        if (cp) v *= cp[ic];
        const __nv_bfloat16 hb=__float2bfloat16(v);
        const __nv_bfloat16 lb=__float2bfloat16(v-__bfloat162float(hb));
        const uint32_t off=(uint32_t)oc*128+(uint32_t)ic*2;
        const uint32_t sw=off^((off>>3)&0x70);
        dst[sw>>1]=hb;
        dst[4096+(sw>>1)]=lb;
    }
}

// ---------------- ingest: x fp32 -> atile ----------------
__global__ __launch_bounds__(256) void ingest_kernel(const float* __restrict__ x,
                                                     __nv_bfloat16* __restrict__ xat){
    extern __shared__ char smI[];
    float* raw = (float*)smI;
    char*  at  = smI + 32768;
    const int tid=threadIdx.x, h=blockIdx.x, b=blockIdx.y;
    for (int i=tid;i<CC*WW;i+=256){
        const int ic=i>>7, w=i&127;
        raw[i] = x[(((size_t)b*CC+ic)*HH+h)*WW + w];
    }
    __syncthreads();
    const int w=tid&127, half=tid>>7;
    #pragma unroll
    for (int k=0;k<16;k++){
        const int ic=half*32+2*k;
        uint32_t hp, lp;
        split_pack(raw[ic*WW+w], raw[(ic+1)*WW+w], hp, lp);
        const uint32_t ro = (uint32_t)w*128 + ((uint32_t)((ic>>3)^(w&7))<<4) + (uint32_t)(ic&7)*2;
        *(uint32_t*)(at + ro) = hp;
        *(uint32_t*)(at + 16384 + ro) = lp;
    }
    __syncthreads();
    uint4* dst=(uint4*)(xat + (size_t)(b*HH+h)*16384);
    const uint4* src=(const uint4*)at;
    #pragma unroll
    for (int j=0;j<8;j++) dst[tid+j*256]=src[tid+j*256];
}

// ---------------- shared conv machinery ----------------
__device__ __forceinline__ void zero_pads(char* sm){
    const int tid=threadIdx.x;
    if (tid<128){
        const int buf=tid>>6, r1=tid&63;
        const int plane=r1>>5, r2=r1&31;
        const int pr=r2>>3, c=r2&7;
        const int row=(pr<2)? pr : (128+pr);
        ((uint4*)(sm + buf*ASZU + plane*ALOU + row*128))[c]=make_uint4(0,0,0,0);
    }
}
__device__ __forceinline__ void issueA_row(uint32_t sb, const char* abase, int arow, int buf){
    const int tid=threadIdx.x;
    const int sz=(arow>=0 && arow<HH)?16:0;
    const int rc=arow<0?0:(arow>127?127:arow);
    const char* src=abase+(size_t)rc*32768;
    const uint32_t d0=sb+(uint32_t)buf*ASZU + 2*128;
    #pragma unroll
    for (int j=0;j<4;j++){
        const int c=tid+j*256;
        asm volatile("cp.async.cg.shared.global [%0], [%1], 16, %2;"
            :: "r"(d0+c*16), "l"(src+c*16), "r"(sz) : "memory");
        asm volatile("cp.async.cg.shared.global [%0], [%1], 16, %2;"
            :: "r"(d0+ALOU+c*16), "l"(src+16384+c*16), "r"(sz) : "memory");
    }
}
__device__ __forceinline__ void issueB_tile(uint32_t sb, const __nv_bfloat16* bptr, int buf){
    const int tid=threadIdx.x;
    const char* src=(const char*)bptr;
    const uint32_t d0=sb+BOFFU+(uint32_t)buf*16384;
    #pragma unroll
    for (int j=0;j<4;j++){
        const int c=tid+j*256;
        asm volatile("cp.async.cg.shared.global [%0], [%1], 16;"
            :: "r"(d0+c*16), "l"(src+c*16) : "memory");
    }
}

__device__ __forceinline__ void do_tap(float acc[2][4][4], uint32_t aB, uint32_t bB,
                                       int s, int m0, int n0, int l){
    #pragma unroll
    for (int ks=0;ks<4;ks++){
        const int ch = ks*2 + (l>>4);
        uint32_t ah[2][4], al[2][4];
        #pragma unroll
        for (int mt=0;mt<2;mt++){
            const int row = m0+mt*16+s+(l&15);
            const uint32_t ad = aB + (uint32_t)row*128 + ((uint32_t)(ch ^ ((row-2)&7))<<4);
            LDSM4(ah[mt], ad);
            LDSM4(al[mt], ad + ALOU);
        }
        uint32_t bh[2][4], bl[2][4];
        #pragma unroll
        for (int np=0;np<2;np++){
            const int row = n0+np*16+(l&15);
            const uint32_t bd = bB + (uint32_t)row*128 + ((uint32_t)(ch ^ (row&7))<<4);
            LDSM4(bh[np], bd);
            LDSM4(bl[np], bd + 8192);
        }
        #pragma unroll
        for (int mt=0;mt<2;mt++)
            #pragma unroll
            for (int nt=0;nt<4;nt++){
                const uint32_t b0h=bh[nt>>1][nt&1], b1h=bh[nt>>1][2+(nt&1)];
                const uint32_t b0l=bl[nt>>1][nt&1], b1l=bl[nt>>1][2+(nt&1)];
                mma16816(acc[mt][nt], ah[mt], b0h, b1h);
                mma16816(acc[mt][nt], al[mt], b0h, b1h);
                mma16816(acc[mt][nt], ah[mt], b0l, b1l);
            }
    }
}

__device__ __forceinline__ void epilogue(float acc[2][4][4], const Epi& e,
                                         const float* bias3, const float* bias5,
                                         char* sm, int m0, int n0, int l){
    const int tid=threadIdx.x;
    const int h=blockIdx.x, b=blockIdx.y;
    __syncthreads();
    float* os=(float*)sm;
    #pragma unroll
    for (int mt=0;mt<2;mt++)
        #pragma unroll
        for (int nt=0;nt<4;nt++)
            #pragma unroll
            for (int q=0;q<4;q++){
                const int row=m0+mt*16+(l>>2)+((q>>1)<<3);
                const int col=n0+nt*8+((l&3)<<1)+(q&1);
                os[row*65+col]=acc[mt][nt][q];
            }
    __syncthreads();

    const int w=tid&127, oc0=(tid>>7)*32;
    const size_t pix=(size_t)h*WW+w;
    const float mv = e.map? e.map[(size_t)b*HH*WW+pix] : 0.f;
    char* smA2 = sm + BOFFU;
    #pragma unroll 4
    for (int k=0;k<32;k+=2){
        float vv[2];
        #pragma unroll
        for (int s2=0;s2<2;s2++){
            const int oc=oc0+k+s2;
            const size_t idx=((size_t)(b*CC+oc))*HH*WW+pix;
            float v=os[w*65+oc];
            if (e.bias) v+=e.bias[oc];
            if (bias3)  v+=bias3[oc];
            if (bias5)  v+=bias5[oc];
            if (e.act==1)      v=fmaxf(v,0.f);
            else if (e.act==2) v=(v>0.f)?v:0.01f*v;
            if (e.res) v+=e.res[idx];
            if (e.cg)  v*=e.cg[b*CC+oc];
            if (e.map) v=v*mv+e.xres[idx];
            if (e.out) e.out[idx]=v;
            vv[s2]=v;
        }
        if (e.atout){
            const int oc=oc0+k;
            uint32_t hp, lp;
            split_pack(vv[0], vv[1], hp, lp);
            const uint32_t ro = (uint32_t)w*128 + ((uint32_t)((oc>>3)^(w&7))<<4)
                              + (uint32_t)(oc&7)*2;
            *(uint32_t*)(smA2 + ro) = hp;
            *(uint32_t*)(smA2 + 16384 + ro) = lp;
        }
    }
    if (e.atout){
        __syncthreads();
        uint4* dst=(uint4*)(e.atout + (size_t)(b*HH+h)*16384);
        const uint4* src=(const uint4*)smA2;
        #pragma unroll
        for (int j=0;j<8;j++) dst[tid+j*256]=src[tid+j*256];
    }
}

// ---------------- generic runtime-K conv body ----------------
__device__ __forceinline__ void conv_body(const Job& j, char* sm, uint32_t sb){
    const int kd=j.kd, pad=kd>>1, taps=kd*kd;
    const int tid=threadIdx.x, l=tid&31, wid=tid>>5;
    const int m0=(wid&3)*32, n0=(wid>>2)*32;
    const int h=blockIdx.x, b=blockIdx.y;

    zero_pads(sm);
    const char* abase=(const char*)j.ain + (size_t)b*HH*32768;

    float acc[2][4][4];
    #pragma unroll
    for (int mt=0;mt<2;mt++)
        #pragma unroll
        for (int nt=0;nt<4;nt++)
            #pragma unroll
            for (int q=0;q<4;q++) acc[mt][nt][q]=0.f;

    issueA_row(sb, abase, h-pad, 0);
    issueB_tile(sb, j.wt + (size_t)b*j.bstride*8192, 0);
    asm volatile("cp.async.commit_group;" ::: "memory");

    int kh=0, kw=0;
    for (int t=0;t<taps;t++){
        asm volatile("cp.async.wait_group 0;" ::: "memory");
        __syncthreads();
        if (t+1<taps){
            int kwn=kw+1, khn=kh;
            if (kwn==kd){kwn=0; khn++;}
            issueB_tile(sb, j.wt + ((size_t)b*j.bstride + t+1)*8192, (t+1)&1);
            if (kwn==0) issueA_row(sb, abase, h+khn-pad, khn&1);
            asm volatile("cp.async.commit_group;" ::: "memory");
        }
        const int s = 2 + kw - pad;
        do_tap(acc, sb+(uint32_t)(kh&1)*ASZU, sb+BOFFU+(uint32_t)(t&1)*16384, s, m0, n0, l);
        kw++; if (kw==kd){kw=0; kh++;}
    }
    epilogue(acc, j.e, nullptr, nullptr, sm, m0, n0, l);
}

__global__ __launch_bounds__(256,2) void conv_single(Job j){
    extern __shared__ char smraw[];
    const uint32_t sb0=smem_u32(smraw), sb=(sb0+127)&~127u;
    conv_body(j, smraw+(sb-sb0), sb);
}
__global__ __launch_bounds__(256,2) void conv_multi(Job j0, Job j1, Job j2){
    extern __shared__ char smraw[];
    const uint32_t sb0=smem_u32(smraw), sb=(sb0+127)&~127u;
    const Job& j = (blockIdx.z==0)? j0 : (blockIdx.z==1)? j1 : j2;
    conv_body(j, smraw+(sb-sb0), sb);
}

// ---------------- fused MFE second stage: 35-tap K-fused GEMM ----------------
__global__ __launch_bounds__(256,2) void mfeb_kernel(
    const __nv_bfloat16* a1, const __nv_bfloat16* a3, const __nv_bfloat16* a5,
    const __nv_bfloat16* w1, const __nv_bfloat16* w3, const __nv_bfloat16* w5,
    const float* bias3, const float* bias5, Epi e)
{
    extern __shared__ char smraw[];
    const uint32_t sb0=smem_u32(smraw), sb=(sb0+127)&~127u;
    char* sm = smraw + (sb - sb0);

    const int tid=threadIdx.x, l=tid&31, wid=tid>>5;
    const int m0=(wid&3)*32, n0=(wid>>2)*32;
    const int h=blockIdx.x, b=blockIdx.y;

    zero_pads(sm);
    const char* ab1=(const char*)a1 + (size_t)b*HH*32768;
    const char* ab3=(const char*)a3 + (size_t)b*HH*32768;
    const char* ab5=(const char*)a5 + (size_t)b*HH*32768;

    float acc[2][4][4];
    #pragma unroll
    for (int mt=0;mt<2;mt++)
        #pragma unroll
        for (int nt=0;nt<4;nt++)
            #pragma unroll
            for (int q=0;q<4;q++) acc[mt][nt][q]=0.f;

    // schedule: t=0 -> y1 tap; t in [1,10) -> y3; t in [10,35) -> y5
    auto sched=[&](int t, int& srci, int& arow, int& s, int& tapu, int& aord){
        if (t==0){srci=0; arow=h; s=2; tapu=0; aord=0;}
        else if (t<10){const int u=t-1, kh=u/3, kw=u-kh*3;
                       srci=1; arow=h+kh-1; s=1+kw; tapu=u; aord=1+kh;}
        else {const int u=t-10, kh=u/5, kw=u-kh*5;
              srci=2; arow=h+kh-2; s=kw; tapu=u; aord=4+kh;}
    };

    // prologue
    issueA_row(sb, ab1, h, 0);
    issueB_tile(sb, w1, 0);
    asm volatile("cp.async.commit_group;" ::: "memory");

    for (int t=0;t<35;t++){
        asm volatile("cp.async.wait_group 0;" ::: "memory");
        __syncthreads();
        if (t<34){
            int srci, arow, s, tapu, aord;
            sched(t+1, srci, arow, s, tapu, aord);
            const __nv_bfloat16* bp = (srci==0)? w1 :
                                      (srci==1)? w3 + (size_t)tapu*8192
                                               : w5 + (size_t)tapu*8192;
            issueB_tile(sb, bp, (t+1)&1);
            const bool fresh = (srci==1 && tapu%3==0) || (srci==2 && tapu%5==0);
            if (fresh)
                issueA_row(sb, (srci==1)? ab3 : ab5, arow, aord&1);
            asm volatile("cp.async.commit_group;" ::: "memory");
        }
        int srci, arow, s, tapu, aord;
        sched(t, srci, arow, s, tapu, aord);
        do_tap(acc, sb+(uint32_t)(aord&1)*ASZU, sb+BOFFU+(uint32_t)(t&1)*16384, s, m0, n0, l);
    }
    epilogue(acc, e, bias3, bias5, sm, m0, n0, l);
}

// ---------------- stats + channel attention ----------------
__global__ __launch_bounds__(256) void stats_kernel(const float* __restrict__ in,
                                                    float* __restrict__ st){
    const int bc=blockIdx.x;
    const float* p=in+(size_t)bc*HH*WW;
    const int tid=threadIdx.x;
    float mx=-3.4e38f, smv=0.f;
    for (int i=tid;i<HH*WW;i+=256){ const float v=p[i]; mx=fmaxf(mx,v); smv+=v; }
    __shared__ float smx[256], ssm[256];
    smx[tid]=mx; ssm[tid]=smv; __syncthreads();
    for (int s=128;s>0;s>>=1){
        if (tid<s){ smx[tid]=fmaxf(smx[tid],smx[tid+s]); ssm[tid]+=ssm[tid+s]; }
        __syncthreads();
    }
    if (tid==0){ st[bc]=smx[0]; st[BB*CC+bc]=ssm[0]*(1.f/(HH*WW)); }
}

__global__ void cg_kernel(const float* __restrict__ st, const float* __restrict__ cw1,
                          const float* __restrict__ cw2, const float* __restrict__ fw,
                          const float* __restrict__ fb, float* __restrict__ cg){
    const int t=threadIdx.x, b=t>>6, c=t&63;
    float se=0.f;
    #pragma unroll
    for (int hh=0;hh<4;hh++){
        float hm=0.f, ha=0.f;
        for (int i=0;i<CC;i++){
            const float wv=cw1[hh*CC+i];
            hm+=wv*st[b*CC+i]; ha+=wv*st[BB*CC+b*CC+i];
        }
        se+=cw2[c*4+hh]*(fmaxf(hm,0.f)+fmaxf(ha,0.f));
    }
    const float xll=1.f/(1.f+expf(-se));
    cg[t]=fw[1]*(fw[0]*xll+fb[0])+fb[1];
}

static Epi mkEpi(const float* bias, int act, float* out, __nv_bfloat16* atout){
    Epi e; e.bias=bias; e.res=nullptr; e.cg=nullptr;
    e.map=nullptr; e.xres=nullptr; e.out=out; e.atout=atout; e.act=act; return e;
}

extern "C" void kernel_launch(void* const* d_in, const int* in_sizes, int n_in,
                              void* d_out, int out_size)
{
    const float* x    = (const float*)d_in[0];
    const float* cf1  = (const float*)d_in[1];
    const float* cf2  = (const float*)d_in[2];
    const float* map_ = (const float*)d_in[3];
    const float* resw = (const float*)d_in[4];
    const float* resb = (const float*)d_in[5];
    const float* mw1  = (const float*)d_in[6];
    const float* mb1  = (const float*)d_in[7];
    const float* mw3  = (const float*)d_in[8];
    const float* mb3  = (const float*)d_in[9];
    const float* mw5  = (const float*)d_in[10];
    const float* mb5  = (const float*)d_in[11];
    const float* caw1 = (const float*)d_in[12];
    const float* caw2 = (const float*)d_in[13];
    const float* fcw  = (const float*)d_in[14];
    const float* fcb  = (const float*)d_in[15];
    float* out = (float*)d_out;

    float *bo,*bst,*bcg; __nv_bfloat16 *wb,*at0;
    cudaGetSymbolAddress((void**)&bo,  d_buf_o);
    cudaGetSymbolAddress((void**)&bst, d_stats);
    cudaGetSymbolAddress((void**)&bcg, d_cg);
    cudaGetSymbolAddress((void**)&wb,  d_wb);
    cudaGetSymbolAddress((void**)&at0, d_at);
    const size_t ATS = (size_t)BB*HH*16384;
    __nv_bfloat16* at_x  = at0;
    __nv_bfloat16* at_bo = at0 + ATS;
    __nv_bfloat16* at_m1 = at0 + 2*ATS;   // also resblock mid
    __nv_bfloat16* at_m3 = at0 + 3*ATS;
    __nv_bfloat16* at_m5 = at0 + 4*ATS;

    cudaFuncSetAttribute(conv_single, cudaFuncAttributeMaxDynamicSharedMemorySize, SMEMSZ);
    cudaFuncSetAttribute(conv_multi,  cudaFuncAttributeMaxDynamicSharedMemorySize, SMEMSZ);
    cudaFuncSetAttribute(mfeb_kernel, cudaFuncAttributeMaxDynamicSharedMemorySize, SMEMSZ);
    cudaFuncSetAttribute(ingest_kernel, cudaFuncAttributeMaxDynamicSharedMemorySize, 65536);

    const float SCALE = 1.0f/24.0f;

    // weight prep (cond folded for res convs)
    prep2<<<dim3(9,4,10), 256>>>(resw,                    cf1, SCALE, 9, 0);    // [0,360)
    prep2<<<dim3(9,4,8),  256>>>(resw+(size_t)10*CC*CC*9, cf2, SCALE, 9, 360);  // [360,648)
    prep2<<<dim3(1,1,10), 256>>>(mw1,  nullptr, 1.f, 1,  648);                  // [648,658)
    prep2<<<dim3(9,1,10), 256>>>(mw3,  nullptr, 1.f, 9,  658);                  // [658,748)
    prep2<<<dim3(25,1,10),256>>>(mw5,  nullptr, 1.f, 25, 748);                  // [748,998)

    ingest_kernel<<<dim3(HH,BB),256,65536>>>(x, at_x);

    auto res_tb=[](int c){ return (c<10)? c*4*9 : 360+(c-10)*4*9; };

    const dim3 grid(HH,BB), grid3(HH,BB,3), blk(256);
    const int mfe_after[9]={-1,0,-1,1,-1,2,-1,3,4};
    const float* cur=x;
    __nv_bfloat16* cur_at=at_x;

    for (int i=0;i<9;i++){
        const int c0=i*2, c1=i*2+1;

        Job j1; j1.ain=cur_at; j1.wt=wb+(size_t)res_tb(c0)*8192; j1.bstride=9; j1.kd=3;
        j1.e=mkEpi(resb+(size_t)c0*CC, 1, nullptr, at_m1);
        conv_single<<<grid,blk,SMEMSZ>>>(j1);

        Job j2; j2.ain=at_m1; j2.wt=wb+(size_t)res_tb(c1)*8192; j2.bstride=9; j2.kd=3;
        j2.e=mkEpi(resb+(size_t)c1*CC, 0, bo, at_bo);
        j2.e.res=cur;
        conv_single<<<grid,blk,SMEMSZ>>>(j2);
        cur=bo; cur_at=at_bo;

        const int j=mfe_after[i];
        if (j>=0){
            const int ca=j*2, cb=j*2+1;

            // merged a-stage: 3 branches in one launch
            Job a1; a1.ain=cur_at; a1.wt=wb+(size_t)(648+ca)*8192;    a1.bstride=0; a1.kd=1;
            a1.e=mkEpi(mb1+(size_t)ca*CC, 2, nullptr, at_m1);
            Job a3; a3.ain=cur_at; a3.wt=wb+(size_t)(658+ca*9)*8192;  a3.bstride=0; a3.kd=3;
            a3.e=mkEpi(mb3+(size_t)ca*CC, 2, nullptr, at_m3);
            Job a5; a5.ain=cur_at; a5.wt=wb+(size_t)(748+ca*25)*8192; a5.bstride=0; a5.kd=5;
            a5.e=mkEpi(mb5+(size_t)ca*CC, 2, nullptr, at_m5);
            conv_multi<<<grid3,blk,SMEMSZ>>>(a1,a3,a5);

            stats_kernel<<<BB*CC,256>>>(cur,bst);
            cg_kernel<<<1,256>>>(bst, caw1+(size_t)j*4*CC, caw2+(size_t)j*CC*4,
                                 fcw+j*2, fcb+j*2, bcg);

            // fused b-stage: one 35-tap GEMM
            Epi eb=mkEpi(mb1+(size_t)cb*CC, 0, (j==4)?out:bo, (j==4)?nullptr:at_bo);
            eb.cg=bcg;
            if (j==4){ eb.map=map_; eb.xres=x; }
            mfeb_kernel<<<grid,blk,SMEMSZ>>>(
                at_m1, at_m3, at_m5,
                wb+(size_t)(648+cb)*8192, wb+(size_t)(658+cb*9)*8192, wb+(size_t)(748+cb*25)*8192,
                mb3+(size_t)cb*CC, mb5+(size_t)cb*CC, eb);
            cur=bo; cur_at=at_bo;
        }
    }
}